// round 15
// baseline (speedup 1.0000x reference)
#include <cuda_runtime.h>
#include <cuda_fp16.h>
#include <math.h>
#include <stdint.h>

#define DIM 768
#define NHEAD 16
#define HD 48
#define SEQ 2048
#define ATTN_SCALE 0.14433756729740643f  // 1/sqrt(48)

#define BQ 128
#define BKV 64
#define NIT (SEQ / BKV)   // 32

// ---------------------------------------------------------------------------
// Scratch (device globals: allocation-guard-safe). Everything fp16.
// ---------------------------------------------------------------------------
__device__ __half g_x16[8192 * DIM];
__device__ __half g_w16[4 * DIM * DIM];   // Wq, Wk, Wv, Wo
__device__ __half g_q[8192 * DIM];
__device__ __half g_k[8192 * DIM];
__device__ __half g_v[8192 * DIM];
__device__ __half g_ao[8192 * DIM];

// ---------------------------------------------------------------------------
// helpers
// ---------------------------------------------------------------------------
__device__ __forceinline__ uint32_t pk2(float lo, float hi) {
    __half2 h = __float22half2_rn(make_float2(lo, hi));
    return *(uint32_t*)&h;
}

__device__ __forceinline__ float fexp2(float x) {
    float y;
    asm("ex2.approx.f32 %0, %1;" : "=f"(y) : "f"(x));
    return y;
}

__device__ __forceinline__ uint32_t prmt(uint32_t a, uint32_t b, uint32_t s) {
    uint32_t r;
    asm("prmt.b32 %0, %1, %2, %3;" : "=r"(r) : "r"(a), "r"(b), "r"(s));
    return r;
}

// D = A(16x16, row) * B(16x8, col) + D, fp16 in, fp32 accum
__device__ __forceinline__ void mma_f16(float* c, const uint32_t* a,
                                        uint32_t b0, uint32_t b1) {
    asm volatile(
        "mma.sync.aligned.m16n8k16.row.col.f32.f16.f16.f32 "
        "{%0,%1,%2,%3}, {%4,%5,%6,%7}, {%8,%9}, {%0,%1,%2,%3};\n"
        : "+f"(c[0]), "+f"(c[1]), "+f"(c[2]), "+f"(c[3])
        : "r"(a[0]), "r"(a[1]), "r"(a[2]), "r"(a[3]), "r"(b0), "r"(b1));
}

// ---------------------------------------------------------------------------
// fp32 -> fp16 conversion kernels (prep; run once per launch)
// ---------------------------------------------------------------------------
__global__ __launch_bounds__(256) void conv_x_f16(
    const float4* __restrict__ in, uint2* __restrict__ out)
{
    int i = blockIdx.x * 256 + threadIdx.x;   // over 1572864 float4
    float4 f = in[i];
    out[i] = make_uint2(pk2(f.x, f.y), pk2(f.z, f.w));
}

__global__ __launch_bounds__(256) void conv_w_f16(
    const float* __restrict__ w0, const float* __restrict__ w1,
    const float* __restrict__ w2, const float* __restrict__ w3,
    __half* __restrict__ dst)
{
    const float* src = (blockIdx.y == 0) ? w0 : (blockIdx.y == 1) ? w1
                     : (blockIdx.y == 2) ? w2 : w3;
    int i = blockIdx.x * 256 + threadIdx.x;   // over 147456 float4 per matrix
    float4 f = ((const float4*)src)[i];
    ((uint2*)(dst + (size_t)blockIdx.y * (DIM * DIM)))[i] =
        make_uint2(pk2(f.x, f.y), pk2(f.z, f.w));
}

// ---------------------------------------------------------------------------
// GEMM v3 (all-fp16 inputs, fp32 accum): C[m][n] = sum_k A[m][k]*W[n][k]+b[n]
// Block 128x128, bk=32, 256 threads = 8 warps (2M x 4N). uint4 LDG staging
// (no conversion), register prefetch, 2 CTAs/SM.
// Shared [row][20] words (16 data + 4 pad): frag pattern conflict-free.
// ---------------------------------------------------------------------------
__global__ __launch_bounds__(256, 2) void gemm_ff16(
    const __half* __restrict__ A, const __half* __restrict__ W,
    const float* __restrict__ bias, void* __restrict__ C,
    int M, int N, int K, int f16_out)
{
    __shared__ __align__(16) uint32_t As[128 * 20];
    __shared__ __align__(16) uint32_t Ws[128 * 20];

    const int tid  = threadIdx.x;
    const int lane = tid & 31;
    const int warp = tid >> 5;
    const int wm   = (warp >> 2) * 64;
    const int wn   = (warp & 3) * 32;
    const int g    = lane >> 2;
    const int tq   = lane & 3;

    const int bm = blockIdx.y * 128;
    const int bn = blockIdx.x * 128;

    const int Kw = K >> 1;   // words per row

    const uint32_t* Aw = (const uint32_t*)A;
    const uint32_t* Ww = (const uint32_t*)W;

    // staging: 128 rows x 4 uint4(=16 words) -> 512 slots, 2 per thread
    float acc[4][4][4];
#pragma unroll
    for (int mi = 0; mi < 4; mi++)
#pragma unroll
        for (int ni = 0; ni < 4; ni++)
#pragma unroll
            for (int j = 0; j < 4; j++) acc[mi][ni][j] = 0.f;

    uint4 pa[2], pw[2];
#pragma unroll
    for (int s = 0; s < 2; s++) {
        int idx = tid + s * 256;
        int row = idx >> 2, c4 = (idx & 3) << 2;
        pa[s] = *(const uint4*)(Aw + (size_t)(bm + row) * Kw + c4);
        pw[s] = *(const uint4*)(Ww + (size_t)(bn + row) * Kw + c4);
    }

    for (int k0w = 0; k0w < Kw; k0w += 16) {
#pragma unroll
        for (int s = 0; s < 2; s++) {
            int idx = tid + s * 256;
            int row = idx >> 2, c4 = (idx & 3) << 2;
            *(uint4*)&As[row * 20 + c4] = pa[s];
            *(uint4*)&Ws[row * 20 + c4] = pw[s];
        }
        __syncthreads();

        if (k0w + 16 < Kw) {
#pragma unroll
            for (int s = 0; s < 2; s++) {
                int idx = tid + s * 256;
                int row = idx >> 2, c4 = (idx & 3) << 2;
                pa[s] = *(const uint4*)(Aw + (size_t)(bm + row) * Kw + k0w + 16 + c4);
                pw[s] = *(const uint4*)(Ww + (size_t)(bn + row) * Kw + k0w + 16 + c4);
            }
        }

#pragma unroll
        for (int kt = 0; kt < 2; kt++) {
            const int kwb = kt * 8;
            uint32_t af[4][4], bf[4][2];
#pragma unroll
            for (int mi = 0; mi < 4; mi++) {
                const int m = wm + mi * 16;
                af[mi][0] = As[(m + g) * 20 + kwb + tq];
                af[mi][1] = As[(m + 8 + g) * 20 + kwb + tq];
                af[mi][2] = As[(m + g) * 20 + kwb + 4 + tq];
                af[mi][3] = As[(m + 8 + g) * 20 + kwb + 4 + tq];
            }
#pragma unroll
            for (int ni = 0; ni < 4; ni++) {
                const int n = wn + ni * 8;
                bf[ni][0] = Ws[(n + g) * 20 + kwb + tq];
                bf[ni][1] = Ws[(n + g) * 20 + kwb + 4 + tq];
            }
#pragma unroll
            for (int mi = 0; mi < 4; mi++)
#pragma unroll
                for (int ni = 0; ni < 4; ni++)
                    mma_f16(acc[mi][ni], af[mi], bf[ni][0], bf[ni][1]);
        }
        __syncthreads();
    }

    if (f16_out) {
        uint32_t* C16 = (uint32_t*)C;
#pragma unroll
        for (int ni = 0; ni < 4; ni++) {
            const int col = bn + wn + ni * 8 + 2 * tq;
            const float2 bb = *(const float2*)(bias + col);
#pragma unroll
            for (int mi = 0; mi < 4; mi++) {
                const int row = bm + wm + mi * 16 + g;
                C16[((size_t)row * N + col) >> 1] =
                    pk2(acc[mi][ni][0] + bb.x, acc[mi][ni][1] + bb.y);
                C16[((size_t)(row + 8) * N + col) >> 1] =
                    pk2(acc[mi][ni][2] + bb.x, acc[mi][ni][3] + bb.y);
            }
        }
    } else {
        float* Cf = (float*)C;
#pragma unroll
        for (int ni = 0; ni < 4; ni++) {
            const int col = bn + wn + ni * 8 + 2 * tq;
            const float2 bb = *(const float2*)(bias + col);
#pragma unroll
            for (int mi = 0; mi < 4; mi++) {
                const int row = bm + wm + mi * 16 + g;
                float2 v0, v1;
                v0.x = acc[mi][ni][0] + bb.x;
                v0.y = acc[mi][ni][1] + bb.y;
                v1.x = acc[mi][ni][2] + bb.x;
                v1.y = acc[mi][ni][3] + bb.y;
                *(float2*)(Cf + (size_t)row * N + col)       = v0;
                *(float2*)(Cf + (size_t)(row + 8) * N + col) = v1;
            }
        }
    }
}

// ---------------------------------------------------------------------------
// Flash attention v12 = v11b with fp16 output (feeds fp16 O-proj GEMM).
// No online max, tensor-pipe l, double-buffered K/V, one barrier/iter.
//
// Shared (uint32 f16x2 words):
//   Qs[128][28]     ofs 0      3584
//   Ks[2][64][28]   ofs 3584   3584
//   Vt[2][56][36]   ofs 7168   4032  (row 48 = ones per buffer)
// total 11200 words = 44800 bytes; 2 CTAs/SM.
// ---------------------------------------------------------------------------
__global__ __launch_bounds__(256, 2) void flash_attn_f16_v12(
    const __half* __restrict__ Q, const __half* __restrict__ K,
    const __half* __restrict__ V, __half* __restrict__ O)
{
    extern __shared__ uint32_t usm[];
    uint32_t* Qs = usm;              // [128][28]
    uint32_t* Ks = usm + 3584;       // [2][64][28]
    uint32_t* Vt = usm + 7168;       // [2][56][36]

    const int tid  = threadIdx.x;
    const int lane = tid & 31;
    const int w    = tid >> 5;
    const int g    = lane >> 2;
    const int tq   = lane & 3;
    const int qb   = w * 16;

    const int h  = blockIdx.y;
    const int b  = blockIdx.z;
    const int q0 = blockIdx.x * BQ;

    const uint32_t* Qw = (const uint32_t*)Q + ((size_t)(b * SEQ + q0)) * 384 + h * 24;
    const uint32_t* Kw = (const uint32_t*)K + (size_t)b * SEQ * 384 + h * 24;
    const uint32_t* Vw = (const uint32_t*)V + (size_t)b * SEQ * 384 + h * 24;

    int kr[3], ku[3], vj[3], vdp[3];
#pragma unroll
    for (int i = 0; i < 3; i++) {
        int idx = tid + i * 256;
        kr[i] = idx / 12; ku[i] = idx % 12;
        vj[i] = idx / 24; vdp[i] = idx % 24;
    }

    // ---- stage Q: 128 rows x 12 uint2 = 1536 slots -> 6 iterations ----
#pragma unroll
    for (int i = 0; i < 6; i++) {
        int idx = tid + i * 256;
        int r = idx / 12, u = idx % 12;
        uint2 qv = *(const uint2*)(Qw + (size_t)r * 384 + u * 2);
        *(uint2*)&Qs[r * 28 + u * 2] = qv;
    }
    // ---- init Vt ones/zero rows 48..55 in BOTH buffers ----
    for (int t = tid; t < 576; t += 256) {
        int bufi = t / 288;
        int rr   = (t % 288) / 36 + 48;
        int cc   = t % 36;
        Vt[bufi * 2016 + rr * 36 + cc] = (rr == 48) ? pk2(1.f, 1.f) : 0u;
    }

    // ---- prefetch K/V tile 0 ----
    uint2 kpre[3];
    uint32_t vp0[3], vp1[3];
#pragma unroll
    for (int i = 0; i < 3; i++) {
        kpre[i] = *(const uint2*)(Kw + (size_t)kr[i] * 384 + ku[i] * 2);
        vp0[i]  = Vw[(size_t)(2 * vj[i])     * 384 + vdp[i]];
        vp1[i]  = Vw[(size_t)(2 * vj[i] + 1) * 384 + vdp[i]];
    }
    __syncthreads();

    uint32_t qf[3][4];
#pragma unroll
    for (int kt = 0; kt < 3; kt++) {
        const int kwb = kt * 8;
        qf[kt][0] = Qs[(qb + g) * 28 + kwb + tq];
        qf[kt][1] = Qs[(qb + 8 + g) * 28 + kwb + tq];
        qf[kt][2] = Qs[(qb + g) * 28 + kwb + 4 + tq];
        qf[kt][3] = Qs[(qb + 8 + g) * 28 + kwb + 4 + tq];
    }

    float oacc[7][4];
#pragma unroll
    for (int ni = 0; ni < 7; ni++)
#pragma unroll
        for (int j = 0; j < 4; j++) oacc[ni][j] = 0.f;

    const float CE = ATTN_SCALE * 1.4426950408889634f;

    for (int it = 0; it < NIT; it++) {
        uint32_t* Ksb = Ks + (it & 1) * 1792;
        uint32_t* Vtb = Vt + (it & 1) * 2016;

#pragma unroll
        for (int i = 0; i < 3; i++) {
            *(uint2*)&Ksb[kr[i] * 28 + ku[i] * 2] = kpre[i];
            Vtb[(2 * vdp[i])     * 36 + vj[i]] = prmt(vp0[i], vp1[i], 0x5410u);
            Vtb[(2 * vdp[i] + 1) * 36 + vj[i]] = prmt(vp0[i], vp1[i], 0x7632u);
        }
        __syncthreads();

        if (it + 1 < NIT) {
            const int kv1 = (it + 1) * BKV;
#pragma unroll
            for (int i = 0; i < 3; i++) {
                kpre[i] = *(const uint2*)(Kw + (size_t)(kv1 + kr[i]) * 384 + ku[i] * 2);
                vp0[i]  = Vw[(size_t)(kv1 + 2 * vj[i])     * 384 + vdp[i]];
                vp1[i]  = Vw[(size_t)(kv1 + 2 * vj[i] + 1) * 384 + vdp[i]];
            }
        }

        float sacc[8][4];
#pragma unroll
        for (int ni = 0; ni < 8; ni++)
#pragma unroll
            for (int j = 0; j < 4; j++) sacc[ni][j] = 0.f;

#pragma unroll
        for (int kt = 0; kt < 3; kt++) {
            const int kwb = kt * 8;
#pragma unroll
            for (int ni = 0; ni < 8; ni++) {
                const int n = ni * 8;
                uint32_t b0 = Ksb[(n + g) * 28 + kwb + tq];
                uint32_t b1 = Ksb[(n + g) * 28 + kwb + 4 + tq];
                mma_f16(sacc[ni], qf[kt], b0, b1);
            }
        }

        uint32_t pf[4][4];
#pragma unroll
        for (int kt = 0; kt < 4; kt++) {
            float p00 = fexp2(sacc[2*kt][0]   * CE);
            float p01 = fexp2(sacc[2*kt][1]   * CE);
            float p02 = fexp2(sacc[2*kt][2]   * CE);
            float p03 = fexp2(sacc[2*kt][3]   * CE);
            float p10 = fexp2(sacc[2*kt+1][0] * CE);
            float p11 = fexp2(sacc[2*kt+1][1] * CE);
            float p12 = fexp2(sacc[2*kt+1][2] * CE);
            float p13 = fexp2(sacc[2*kt+1][3] * CE);
            pf[kt][0] = pk2(p00, p01);
            pf[kt][1] = pk2(p02, p03);
            pf[kt][2] = pk2(p10, p11);
            pf[kt][3] = pk2(p12, p13);
        }

#pragma unroll
        for (int kt = 0; kt < 4; kt++) {
            const int kwb = kt * 8;
#pragma unroll
            for (int ni = 0; ni < 7; ni++) {
                const int n = ni * 8;
                uint32_t b0 = Vtb[(n + g) * 36 + kwb + tq];
                uint32_t b1 = Vtb[(n + g) * 36 + kwb + 4 + tq];
                mma_f16(oacc[ni], pf[kt], b0, b1);
            }
        }
    }

    // ---- epilogue (fp16 output) ----
    const float l0 = __shfl_sync(0xffffffffu, oacc[6][0], lane & ~3);
    const float l1 = __shfl_sync(0xffffffffu, oacc[6][2], lane & ~3);
    const float inv0 = 1.f / l0;
    const float inv1 = 1.f / l1;
    uint32_t* Ow = (uint32_t*)O + ((size_t)(b * SEQ + q0 + qb)) * 384 + h * 24;
#pragma unroll
    for (int ni = 0; ni < 6; ni++) {
        const int cw = ni * 4 + tq;   // word column within head
        Ow[(size_t)g * 384 + cw] =
            pk2(oacc[ni][0] * inv0, oacc[ni][1] * inv0);
        Ow[(size_t)(g + 8) * 384 + cw] =
            pk2(oacc[ni][2] * inv1, oacc[ni][3] * inv1);
    }
}

// ---------------------------------------------------------------------------
// launch
// ---------------------------------------------------------------------------
extern "C" void kernel_launch(void* const* d_in, const int* in_sizes, int n_in,
                              void* d_out, int out_size)
{
    const float* x  = (const float*)d_in[0];
    const float* Wq = (const float*)d_in[1];
    const float* bq = (const float*)d_in[2];
    const float* Wk = (const float*)d_in[3];
    const float* bk = (const float*)d_in[4];
    const float* Wv = (const float*)d_in[5];
    const float* bv = (const float*)d_in[6];
    const float* Wo = (const float*)d_in[7];
    const float* bo = (const float*)d_in[8];
    float* out = (float*)d_out;

    const int M = in_sizes[0] / DIM;   // B*S = 8192
    const int B = M / SEQ;             // 4

    __half *x16, *w16, *qp, *kp, *vp, *aop;
    cudaGetSymbolAddress((void**)&x16, g_x16);
    cudaGetSymbolAddress((void**)&w16, g_w16);
    cudaGetSymbolAddress((void**)&qp,  g_q);
    cudaGetSymbolAddress((void**)&kp,  g_k);
    cudaGetSymbolAddress((void**)&vp,  g_v);
    cudaGetSymbolAddress((void**)&aop, g_ao);

    const int attn_smem = 11200 * 4;   // 44800 bytes

    // prep: fp32 -> fp16
    conv_x_f16<<<(M * DIM / 4) / 256, 256>>>((const float4*)x, (uint2*)x16);
    conv_w_f16<<<dim3((DIM * DIM / 4) / 256, 4), 256>>>(Wq, Wk, Wv, Wo, w16);

    dim3 ggrid(DIM / 128, M / 128);    // (6, 64)
    gemm_ff16<<<ggrid, 256>>>(x16, w16 + 0 * DIM * DIM, bq, qp, M, DIM, DIM, 1);
    gemm_ff16<<<ggrid, 256>>>(x16, w16 + 1 * DIM * DIM, bk, kp, M, DIM, DIM, 1);
    gemm_ff16<<<ggrid, 256>>>(x16, w16 + 2 * DIM * DIM, bv, vp, M, DIM, DIM, 1);

    dim3 agrid(SEQ / BQ, NHEAD, B);    // (16, 16, 4)
    flash_attn_f16_v12<<<agrid, 256, attn_smem>>>(qp, kp, vp, aop);

    gemm_ff16<<<ggrid, 256>>>(aop, w16 + 3 * DIM * DIM, bo, out, M, DIM, DIM, 0);
}

// round 16
// speedup vs baseline: 1.0582x; 1.0582x over previous
#include <cuda_runtime.h>
#include <cuda_fp16.h>
#include <math.h>
#include <stdint.h>

#define DIM 768
#define NHEAD 16
#define HD 48
#define SEQ 2048
#define ATTN_SCALE 0.14433756729740643f  // 1/sqrt(48)

#define BQ 128
#define BKV 64
#define NIT (SEQ / BKV)   // 32

// ---------------------------------------------------------------------------
// Scratch (device globals: allocation-guard-safe). Everything fp16.
// ---------------------------------------------------------------------------
__device__ __half g_x16[8192 * DIM];
__device__ __half g_w16[4 * DIM * DIM];   // Wq, Wk, Wv, Wo
__device__ __half g_q[8192 * DIM];
__device__ __half g_k[8192 * DIM];
__device__ __half g_v[8192 * DIM];
__device__ __half g_ao[8192 * DIM];

// ---------------------------------------------------------------------------
// helpers
// ---------------------------------------------------------------------------
__device__ __forceinline__ uint32_t pk2(float lo, float hi) {
    __half2 h = __float22half2_rn(make_float2(lo, hi));
    return *(uint32_t*)&h;
}

__device__ __forceinline__ float fexp2(float x) {
    float y;
    asm("ex2.approx.f32 %0, %1;" : "=f"(y) : "f"(x));
    return y;
}

__device__ __forceinline__ uint32_t prmt(uint32_t a, uint32_t b, uint32_t s) {
    uint32_t r;
    asm("prmt.b32 %0, %1, %2, %3;" : "=r"(r) : "r"(a), "r"(b), "r"(s));
    return r;
}

// D = A(16x16, row) * B(16x8, col) + D, fp16 in, fp32 accum
__device__ __forceinline__ void mma_f16(float* c, const uint32_t* a,
                                        uint32_t b0, uint32_t b1) {
    asm volatile(
        "mma.sync.aligned.m16n8k16.row.col.f32.f16.f16.f32 "
        "{%0,%1,%2,%3}, {%4,%5,%6,%7}, {%8,%9}, {%0,%1,%2,%3};\n"
        : "+f"(c[0]), "+f"(c[1]), "+f"(c[2]), "+f"(c[3])
        : "r"(a[0]), "r"(a[1]), "r"(a[2]), "r"(a[3]), "r"(b0), "r"(b1));
}

// ---------------------------------------------------------------------------
// fp32 -> fp16 conversion kernels (prep; run once per launch)
// ---------------------------------------------------------------------------
__global__ __launch_bounds__(256) void conv_x_f16(
    const float4* __restrict__ in, uint2* __restrict__ out)
{
    int i = blockIdx.x * 256 + threadIdx.x;
    float4 f = in[i];
    out[i] = make_uint2(pk2(f.x, f.y), pk2(f.z, f.w));
}

__global__ __launch_bounds__(256) void conv_w_f16(
    const float* __restrict__ w0, const float* __restrict__ w1,
    const float* __restrict__ w2, const float* __restrict__ w3,
    __half* __restrict__ dst)
{
    const float* src = (blockIdx.y == 0) ? w0 : (blockIdx.y == 1) ? w1
                     : (blockIdx.y == 2) ? w2 : w3;
    int i = blockIdx.x * 256 + threadIdx.x;
    float4 f = ((const float4*)src)[i];
    ((uint2*)(dst + (size_t)blockIdx.y * (DIM * DIM)))[i] =
        make_uint2(pk2(f.x, f.y), pk2(f.z, f.w));
}

// ---------------------------------------------------------------------------
// Fused QKV projection GEMM (all-fp16, fp32 accum, fp16 out).
// grid.x in [0,18): mat = bx/6 selects {Wq,Wk,Wv}/{bq,bk,bv}/{q,k,v},
// bn = (bx%6)*128. One launch = 1152 CTAs -> 3.9 waves (vs 3 x 1.3).
// ---------------------------------------------------------------------------
__global__ __launch_bounds__(256, 2) void gemm_qkv_fused(
    const __half* __restrict__ A, const __half* __restrict__ Wall,
    const float* __restrict__ bq, const float* __restrict__ bk,
    const float* __restrict__ bv,
    __half* __restrict__ Cq, __half* __restrict__ Ck, __half* __restrict__ Cv,
    int M)
{
    __shared__ __align__(16) uint32_t As[128 * 20];
    __shared__ __align__(16) uint32_t Ws[128 * 20];

    const int tid  = threadIdx.x;
    const int lane = tid & 31;
    const int warp = tid >> 5;
    const int wm   = (warp >> 2) * 64;
    const int wn   = (warp & 3) * 32;
    const int g    = lane >> 2;
    const int tq   = lane & 3;

    const int mat = blockIdx.x / 6;
    const int bn  = (blockIdx.x % 6) * 128;
    const int bm  = blockIdx.y * 128;

    const float* bias = (mat == 0) ? bq : (mat == 1) ? bk : bv;
    uint32_t* C16 = (uint32_t*)((mat == 0) ? Cq : (mat == 1) ? Ck : Cv);
    const uint32_t* Aw = (const uint32_t*)A;
    const uint32_t* Ww = (const uint32_t*)(Wall + (size_t)mat * DIM * DIM);

    const int Kw = DIM >> 1;   // 384 words per row

    float acc[4][4][4];
#pragma unroll
    for (int mi = 0; mi < 4; mi++)
#pragma unroll
        for (int ni = 0; ni < 4; ni++)
#pragma unroll
            for (int j = 0; j < 4; j++) acc[mi][ni][j] = 0.f;

    uint4 pa[2], pw[2];
#pragma unroll
    for (int s = 0; s < 2; s++) {
        int idx = tid + s * 256;
        int row = idx >> 2, c4 = (idx & 3) << 2;
        pa[s] = *(const uint4*)(Aw + (size_t)(bm + row) * Kw + c4);
        pw[s] = *(const uint4*)(Ww + (size_t)(bn + row) * Kw + c4);
    }

    for (int k0w = 0; k0w < Kw; k0w += 16) {
#pragma unroll
        for (int s = 0; s < 2; s++) {
            int idx = tid + s * 256;
            int row = idx >> 2, c4 = (idx & 3) << 2;
            *(uint4*)&As[row * 20 + c4] = pa[s];
            *(uint4*)&Ws[row * 20 + c4] = pw[s];
        }
        __syncthreads();

        if (k0w + 16 < Kw) {
#pragma unroll
            for (int s = 0; s < 2; s++) {
                int idx = tid + s * 256;
                int row = idx >> 2, c4 = (idx & 3) << 2;
                pa[s] = *(const uint4*)(Aw + (size_t)(bm + row) * Kw + k0w + 16 + c4);
                pw[s] = *(const uint4*)(Ww + (size_t)(bn + row) * Kw + k0w + 16 + c4);
            }
        }

#pragma unroll
        for (int kt = 0; kt < 2; kt++) {
            const int kwb = kt * 8;
            uint32_t af[4][4], bf[4][2];
#pragma unroll
            for (int mi = 0; mi < 4; mi++) {
                const int m = wm + mi * 16;
                af[mi][0] = As[(m + g) * 20 + kwb + tq];
                af[mi][1] = As[(m + 8 + g) * 20 + kwb + tq];
                af[mi][2] = As[(m + g) * 20 + kwb + 4 + tq];
                af[mi][3] = As[(m + 8 + g) * 20 + kwb + 4 + tq];
            }
#pragma unroll
            for (int ni = 0; ni < 4; ni++) {
                const int n = wn + ni * 8;
                bf[ni][0] = Ws[(n + g) * 20 + kwb + tq];
                bf[ni][1] = Ws[(n + g) * 20 + kwb + 4 + tq];
            }
#pragma unroll
            for (int mi = 0; mi < 4; mi++)
#pragma unroll
                for (int ni = 0; ni < 4; ni++)
                    mma_f16(acc[mi][ni], af[mi], bf[ni][0], bf[ni][1]);
        }
        __syncthreads();
    }

#pragma unroll
    for (int ni = 0; ni < 4; ni++) {
        const int col = bn + wn + ni * 8 + 2 * tq;
        const float2 bb = *(const float2*)(bias + col);
#pragma unroll
        for (int mi = 0; mi < 4; mi++) {
            const int row = bm + wm + mi * 16 + g;
            C16[((size_t)row * DIM + col) >> 1] =
                pk2(acc[mi][ni][0] + bb.x, acc[mi][ni][1] + bb.y);
            C16[((size_t)(row + 8) * DIM + col) >> 1] =
                pk2(acc[mi][ni][2] + bb.x, acc[mi][ni][3] + bb.y);
        }
    }
}

// ---------------------------------------------------------------------------
// O-projection GEMM (fp16 in, fp32 out) — unchanged structure.
// ---------------------------------------------------------------------------
__global__ __launch_bounds__(256, 2) void gemm_ff16(
    const __half* __restrict__ A, const __half* __restrict__ W,
    const float* __restrict__ bias, float* __restrict__ C,
    int M, int N, int K)
{
    __shared__ __align__(16) uint32_t As[128 * 20];
    __shared__ __align__(16) uint32_t Ws[128 * 20];

    const int tid  = threadIdx.x;
    const int lane = tid & 31;
    const int warp = tid >> 5;
    const int wm   = (warp >> 2) * 64;
    const int wn   = (warp & 3) * 32;
    const int g    = lane >> 2;
    const int tq   = lane & 3;

    const int bm = blockIdx.y * 128;
    const int bn = blockIdx.x * 128;

    const int Kw = K >> 1;
    const uint32_t* Aw = (const uint32_t*)A;
    const uint32_t* Ww = (const uint32_t*)W;

    float acc[4][4][4];
#pragma unroll
    for (int mi = 0; mi < 4; mi++)
#pragma unroll
        for (int ni = 0; ni < 4; ni++)
#pragma unroll
            for (int j = 0; j < 4; j++) acc[mi][ni][j] = 0.f;

    uint4 pa[2], pw[2];
#pragma unroll
    for (int s = 0; s < 2; s++) {
        int idx = tid + s * 256;
        int row = idx >> 2, c4 = (idx & 3) << 2;
        pa[s] = *(const uint4*)(Aw + (size_t)(bm + row) * Kw + c4);
        pw[s] = *(const uint4*)(Ww + (size_t)(bn + row) * Kw + c4);
    }

    for (int k0w = 0; k0w < Kw; k0w += 16) {
#pragma unroll
        for (int s = 0; s < 2; s++) {
            int idx = tid + s * 256;
            int row = idx >> 2, c4 = (idx & 3) << 2;
            *(uint4*)&As[row * 20 + c4] = pa[s];
            *(uint4*)&Ws[row * 20 + c4] = pw[s];
        }
        __syncthreads();

        if (k0w + 16 < Kw) {
#pragma unroll
            for (int s = 0; s < 2; s++) {
                int idx = tid + s * 256;
                int row = idx >> 2, c4 = (idx & 3) << 2;
                pa[s] = *(const uint4*)(Aw + (size_t)(bm + row) * Kw + k0w + 16 + c4);
                pw[s] = *(const uint4*)(Ww + (size_t)(bn + row) * Kw + k0w + 16 + c4);
            }
        }

#pragma unroll
        for (int kt = 0; kt < 2; kt++) {
            const int kwb = kt * 8;
            uint32_t af[4][4], bf[4][2];
#pragma unroll
            for (int mi = 0; mi < 4; mi++) {
                const int m = wm + mi * 16;
                af[mi][0] = As[(m + g) * 20 + kwb + tq];
                af[mi][1] = As[(m + 8 + g) * 20 + kwb + tq];
                af[mi][2] = As[(m + g) * 20 + kwb + 4 + tq];
                af[mi][3] = As[(m + 8 + g) * 20 + kwb + 4 + tq];
            }
#pragma unroll
            for (int ni = 0; ni < 4; ni++) {
                const int n = wn + ni * 8;
                bf[ni][0] = Ws[(n + g) * 20 + kwb + tq];
                bf[ni][1] = Ws[(n + g) * 20 + kwb + 4 + tq];
            }
#pragma unroll
            for (int mi = 0; mi < 4; mi++)
#pragma unroll
                for (int ni = 0; ni < 4; ni++)
                    mma_f16(acc[mi][ni], af[mi], bf[ni][0], bf[ni][1]);
        }
        __syncthreads();
    }

#pragma unroll
    for (int ni = 0; ni < 4; ni++) {
        const int col = bn + wn + ni * 8 + 2 * tq;
        const float2 bb = *(const float2*)(bias + col);
#pragma unroll
        for (int mi = 0; mi < 4; mi++) {
            const int row = bm + wm + mi * 16 + g;
            float2 v0, v1;
            v0.x = acc[mi][ni][0] + bb.x;
            v0.y = acc[mi][ni][1] + bb.y;
            v1.x = acc[mi][ni][2] + bb.x;
            v1.y = acc[mi][ni][3] + bb.y;
            *(float2*)(C + (size_t)row * N + col)       = v0;
            *(float2*)(C + (size_t)(row + 8) * N + col) = v1;
        }
    }
}

// ---------------------------------------------------------------------------
// Flash attention v12 (unchanged from R14): no online max, tensor-pipe l,
// double-buffered K/V, one barrier/iter, fp16 in/out.
// ---------------------------------------------------------------------------
__global__ __launch_bounds__(256, 2) void flash_attn_f16_v12(
    const __half* __restrict__ Q, const __half* __restrict__ K,
    const __half* __restrict__ V, __half* __restrict__ O)
{
    extern __shared__ uint32_t usm[];
    uint32_t* Qs = usm;              // [128][28]
    uint32_t* Ks = usm + 3584;       // [2][64][28]
    uint32_t* Vt = usm + 7168;       // [2][56][36]

    const int tid  = threadIdx.x;
    const int lane = tid & 31;
    const int w    = tid >> 5;
    const int g    = lane >> 2;
    const int tq   = lane & 3;
    const int qb   = w * 16;

    const int h  = blockIdx.y;
    const int b  = blockIdx.z;
    const int q0 = blockIdx.x * BQ;

    const uint32_t* Qw = (const uint32_t*)Q + ((size_t)(b * SEQ + q0)) * 384 + h * 24;
    const uint32_t* Kw = (const uint32_t*)K + (size_t)b * SEQ * 384 + h * 24;
    const uint32_t* Vw = (const uint32_t*)V + (size_t)b * SEQ * 384 + h * 24;

    int kr[3], ku[3], vj[3], vdp[3];
#pragma unroll
    for (int i = 0; i < 3; i++) {
        int idx = tid + i * 256;
        kr[i] = idx / 12; ku[i] = idx % 12;
        vj[i] = idx / 24; vdp[i] = idx % 24;
    }

#pragma unroll
    for (int i = 0; i < 6; i++) {
        int idx = tid + i * 256;
        int r = idx / 12, u = idx % 12;
        uint2 qv = *(const uint2*)(Qw + (size_t)r * 384 + u * 2);
        *(uint2*)&Qs[r * 28 + u * 2] = qv;
    }
    for (int t = tid; t < 576; t += 256) {
        int bufi = t / 288;
        int rr   = (t % 288) / 36 + 48;
        int cc   = t % 36;
        Vt[bufi * 2016 + rr * 36 + cc] = (rr == 48) ? pk2(1.f, 1.f) : 0u;
    }

    uint2 kpre[3];
    uint32_t vp0[3], vp1[3];
#pragma unroll
    for (int i = 0; i < 3; i++) {
        kpre[i] = *(const uint2*)(Kw + (size_t)kr[i] * 384 + ku[i] * 2);
        vp0[i]  = Vw[(size_t)(2 * vj[i])     * 384 + vdp[i]];
        vp1[i]  = Vw[(size_t)(2 * vj[i] + 1) * 384 + vdp[i]];
    }
    __syncthreads();

    uint32_t qf[3][4];
#pragma unroll
    for (int kt = 0; kt < 3; kt++) {
        const int kwb = kt * 8;
        qf[kt][0] = Qs[(qb + g) * 28 + kwb + tq];
        qf[kt][1] = Qs[(qb + 8 + g) * 28 + kwb + tq];
        qf[kt][2] = Qs[(qb + g) * 28 + kwb + 4 + tq];
        qf[kt][3] = Qs[(qb + 8 + g) * 28 + kwb + 4 + tq];
    }

    float oacc[7][4];
#pragma unroll
    for (int ni = 0; ni < 7; ni++)
#pragma unroll
        for (int j = 0; j < 4; j++) oacc[ni][j] = 0.f;

    const float CE = ATTN_SCALE * 1.4426950408889634f;

    for (int it = 0; it < NIT; it++) {
        uint32_t* Ksb = Ks + (it & 1) * 1792;
        uint32_t* Vtb = Vt + (it & 1) * 2016;

#pragma unroll
        for (int i = 0; i < 3; i++) {
            *(uint2*)&Ksb[kr[i] * 28 + ku[i] * 2] = kpre[i];
            Vtb[(2 * vdp[i])     * 36 + vj[i]] = prmt(vp0[i], vp1[i], 0x5410u);
            Vtb[(2 * vdp[i] + 1) * 36 + vj[i]] = prmt(vp0[i], vp1[i], 0x7632u);
        }
        __syncthreads();

        if (it + 1 < NIT) {
            const int kv1 = (it + 1) * BKV;
#pragma unroll
            for (int i = 0; i < 3; i++) {
                kpre[i] = *(const uint2*)(Kw + (size_t)(kv1 + kr[i]) * 384 + ku[i] * 2);
                vp0[i]  = Vw[(size_t)(kv1 + 2 * vj[i])     * 384 + vdp[i]];
                vp1[i]  = Vw[(size_t)(kv1 + 2 * vj[i] + 1) * 384 + vdp[i]];
            }
        }

        float sacc[8][4];
#pragma unroll
        for (int ni = 0; ni < 8; ni++)
#pragma unroll
            for (int j = 0; j < 4; j++) sacc[ni][j] = 0.f;

#pragma unroll
        for (int kt = 0; kt < 3; kt++) {
            const int kwb = kt * 8;
#pragma unroll
            for (int ni = 0; ni < 8; ni++) {
                const int n = ni * 8;
                uint32_t b0 = Ksb[(n + g) * 28 + kwb + tq];
                uint32_t b1 = Ksb[(n + g) * 28 + kwb + 4 + tq];
                mma_f16(sacc[ni], qf[kt], b0, b1);
            }
        }

        uint32_t pf[4][4];
#pragma unroll
        for (int kt = 0; kt < 4; kt++) {
            float p00 = fexp2(sacc[2*kt][0]   * CE);
            float p01 = fexp2(sacc[2*kt][1]   * CE);
            float p02 = fexp2(sacc[2*kt][2]   * CE);
            float p03 = fexp2(sacc[2*kt][3]   * CE);
            float p10 = fexp2(sacc[2*kt+1][0] * CE);
            float p11 = fexp2(sacc[2*kt+1][1] * CE);
            float p12 = fexp2(sacc[2*kt+1][2] * CE);
            float p13 = fexp2(sacc[2*kt+1][3] * CE);
            pf[kt][0] = pk2(p00, p01);
            pf[kt][1] = pk2(p02, p03);
            pf[kt][2] = pk2(p10, p11);
            pf[kt][3] = pk2(p12, p13);
        }

#pragma unroll
        for (int kt = 0; kt < 4; kt++) {
            const int kwb = kt * 8;
#pragma unroll
            for (int ni = 0; ni < 7; ni++) {
                const int n = ni * 8;
                uint32_t b0 = Vtb[(n + g) * 36 + kwb + tq];
                uint32_t b1 = Vtb[(n + g) * 36 + kwb + 4 + tq];
                mma_f16(oacc[ni], pf[kt], b0, b1);
            }
        }
    }

    const float l0 = __shfl_sync(0xffffffffu, oacc[6][0], lane & ~3);
    const float l1 = __shfl_sync(0xffffffffu, oacc[6][2], lane & ~3);
    const float inv0 = 1.f / l0;
    const float inv1 = 1.f / l1;
    uint32_t* Ow = (uint32_t*)O + ((size_t)(b * SEQ + q0 + qb)) * 384 + h * 24;
#pragma unroll
    for (int ni = 0; ni < 6; ni++) {
        const int cw = ni * 4 + tq;
        Ow[(size_t)g * 384 + cw] =
            pk2(oacc[ni][0] * inv0, oacc[ni][1] * inv0);
        Ow[(size_t)(g + 8) * 384 + cw] =
            pk2(oacc[ni][2] * inv1, oacc[ni][3] * inv1);
    }
}

// ---------------------------------------------------------------------------
// launch
// ---------------------------------------------------------------------------
extern "C" void kernel_launch(void* const* d_in, const int* in_sizes, int n_in,
                              void* d_out, int out_size)
{
    const float* x  = (const float*)d_in[0];
    const float* Wq = (const float*)d_in[1];
    const float* bq = (const float*)d_in[2];
    const float* Wk = (const float*)d_in[3];
    const float* bk = (const float*)d_in[4];
    const float* Wv = (const float*)d_in[5];
    const float* bv = (const float*)d_in[6];
    const float* Wo = (const float*)d_in[7];
    const float* bo = (const float*)d_in[8];
    float* out = (float*)d_out;

    const int M = in_sizes[0] / DIM;   // B*S = 8192
    const int B = M / SEQ;             // 4

    __half *x16, *w16, *qp, *kp, *vp, *aop;
    cudaGetSymbolAddress((void**)&x16, g_x16);
    cudaGetSymbolAddress((void**)&w16, g_w16);
    cudaGetSymbolAddress((void**)&qp,  g_q);
    cudaGetSymbolAddress((void**)&kp,  g_k);
    cudaGetSymbolAddress((void**)&vp,  g_v);
    cudaGetSymbolAddress((void**)&aop, g_ao);

    const int attn_smem = 11200 * 4;   // 44800 bytes

    // prep: fp32 -> fp16
    conv_x_f16<<<(M * DIM / 4) / 256, 256>>>((const float4*)x, (uint2*)x16);
    conv_w_f16<<<dim3((DIM * DIM / 4) / 256, 4), 256>>>(Wq, Wk, Wv, Wo, w16);

    // fused QKV projection: grid (18, 64) = 1152 CTAs
    dim3 qkvgrid(3 * DIM / 128, M / 128);
    gemm_qkv_fused<<<qkvgrid, 256>>>(x16, w16, bq, bk, bv, qp, kp, vp, M);

    dim3 agrid(SEQ / BQ, NHEAD, B);    // (16, 16, 4)
    flash_attn_f16_v12<<<agrid, 256, attn_smem>>>(qp, kp, vp, aop);

    dim3 ogrid(DIM / 128, M / 128);    // (6, 64)
    gemm_ff16<<<ogrid, 256>>>(aop, w16 + 3 * DIM * DIM, bo, out, M, DIM, DIM);
}

// round 17
// speedup vs baseline: 1.0771x; 1.0179x over previous
#include <cuda_runtime.h>
#include <cuda_fp16.h>
#include <math.h>
#include <stdint.h>

#define DIM 768
#define NHEAD 16
#define HD 48
#define SEQ 2048
#define ATTN_SCALE 0.14433756729740643f  // 1/sqrt(48)

#define BQ 128
#define BKV 64
#define NIT (SEQ / BKV)   // 32

// ---------------------------------------------------------------------------
// Scratch (device globals: allocation-guard-safe). Everything fp16.
// ---------------------------------------------------------------------------
__device__ __half g_x16[8192 * DIM];
__device__ __half g_w16[4 * DIM * DIM];   // Wq, Wk, Wv, Wo
__device__ __half g_q[8192 * DIM];
__device__ __half g_k[8192 * DIM];
__device__ __half g_v[8192 * DIM];
__device__ __half g_ao[8192 * DIM];

// ---------------------------------------------------------------------------
// helpers
// ---------------------------------------------------------------------------
__device__ __forceinline__ uint32_t pk2(float lo, float hi) {
    __half2 h = __float22half2_rn(make_float2(lo, hi));
    return *(uint32_t*)&h;
}

__device__ __forceinline__ float fexp2(float x) {
    float y;
    asm("ex2.approx.f32 %0, %1;" : "=f"(y) : "f"(x));
    return y;
}

__device__ __forceinline__ uint32_t prmt(uint32_t a, uint32_t b, uint32_t s) {
    uint32_t r;
    asm("prmt.b32 %0, %1, %2, %3;" : "=r"(r) : "r"(a), "r"(b), "r"(s));
    return r;
}

// D = A(16x16, row) * B(16x8, col) + D, fp16 in, fp32 accum
__device__ __forceinline__ void mma_f16(float* c, const uint32_t* a,
                                        uint32_t b0, uint32_t b1) {
    asm volatile(
        "mma.sync.aligned.m16n8k16.row.col.f32.f16.f16.f32 "
        "{%0,%1,%2,%3}, {%4,%5,%6,%7}, {%8,%9}, {%0,%1,%2,%3};\n"
        : "+f"(c[0]), "+f"(c[1]), "+f"(c[2]), "+f"(c[3])
        : "r"(a[0]), "r"(a[1]), "r"(a[2]), "r"(a[3]), "r"(b0), "r"(b1));
}

// ---------------------------------------------------------------------------
// fp32 -> fp16 conversion kernels (prep; run once per launch)
// ---------------------------------------------------------------------------
__global__ __launch_bounds__(256) void conv_x_f16(
    const float4* __restrict__ in, uint2* __restrict__ out)
{
    int i = blockIdx.x * 256 + threadIdx.x;
    float4 f = in[i];
    out[i] = make_uint2(pk2(f.x, f.y), pk2(f.z, f.w));
}

__global__ __launch_bounds__(256) void conv_w_f16(
    const float* __restrict__ w0, const float* __restrict__ w1,
    const float* __restrict__ w2, const float* __restrict__ w3,
    __half* __restrict__ dst)
{
    const float* src = (blockIdx.y == 0) ? w0 : (blockIdx.y == 1) ? w1
                     : (blockIdx.y == 2) ? w2 : w3;
    int i = blockIdx.x * 256 + threadIdx.x;
    float4 f = ((const float4*)src)[i];
    ((uint2*)(dst + (size_t)blockIdx.y * (DIM * DIM)))[i] =
        make_uint2(pk2(f.x, f.y), pk2(f.z, f.w));
}

// ---------------------------------------------------------------------------
// GEMM mainloop core (shared by fused-QKV and O-proj): all-fp16 inputs,
// fp32 accum, bk=32, DOUBLE-BUFFERED smem, ONE __syncthreads per slab.
// Smem: As[2][128*20], Ws[2][128*20] words = 40960 B -> 2 CTAs/SM.
// ---------------------------------------------------------------------------
#define GEMM_MAINLOOP(Aw, Ww, Kw)                                              \
    uint4 pa[2], pw[2];                                                        \
    _Pragma("unroll")                                                          \
    for (int s = 0; s < 2; s++) {                                              \
        int idx = tid + s * 256;                                               \
        int row = idx >> 2, c4 = (idx & 3) << 2;                               \
        pa[s] = *(const uint4*)((Aw) + (size_t)(bm + row) * (Kw) + c4);        \
        pw[s] = *(const uint4*)((Ww) + (size_t)(bn + row) * (Kw) + c4);        \
    }                                                                          \
    int buf = 0;                                                               \
    for (int k0w = 0; k0w < (Kw); k0w += 16) {                                 \
        uint32_t* Ab = As + buf * 2560;                                        \
        uint32_t* Wb = Ws + buf * 2560;                                        \
        _Pragma("unroll")                                                      \
        for (int s = 0; s < 2; s++) {                                          \
            int idx = tid + s * 256;                                           \
            int row = idx >> 2, c4 = (idx & 3) << 2;                           \
            *(uint4*)&Ab[row * 20 + c4] = pa[s];                               \
            *(uint4*)&Wb[row * 20 + c4] = pw[s];                               \
        }                                                                      \
        __syncthreads();                                                       \
        if (k0w + 16 < (Kw)) {                                                 \
            _Pragma("unroll")                                                  \
            for (int s = 0; s < 2; s++) {                                      \
                int idx = tid + s * 256;                                       \
                int row = idx >> 2, c4 = (idx & 3) << 2;                       \
                pa[s] = *(const uint4*)((Aw) + (size_t)(bm + row) * (Kw)       \
                                        + k0w + 16 + c4);                      \
                pw[s] = *(const uint4*)((Ww) + (size_t)(bn + row) * (Kw)       \
                                        + k0w + 16 + c4);                      \
            }                                                                  \
        }                                                                      \
        _Pragma("unroll")                                                      \
        for (int kt = 0; kt < 2; kt++) {                                       \
            const int kwb = kt * 8;                                            \
            uint32_t af[4][4], bf[4][2];                                       \
            _Pragma("unroll")                                                  \
            for (int mi = 0; mi < 4; mi++) {                                   \
                const int m = wm + mi * 16;                                    \
                af[mi][0] = Ab[(m + g) * 20 + kwb + tq];                       \
                af[mi][1] = Ab[(m + 8 + g) * 20 + kwb + tq];                   \
                af[mi][2] = Ab[(m + g) * 20 + kwb + 4 + tq];                   \
                af[mi][3] = Ab[(m + 8 + g) * 20 + kwb + 4 + tq];               \
            }                                                                  \
            _Pragma("unroll")                                                  \
            for (int ni = 0; ni < 4; ni++) {                                   \
                const int n = wn + ni * 8;                                     \
                bf[ni][0] = Wb[(n + g) * 20 + kwb + tq];                       \
                bf[ni][1] = Wb[(n + g) * 20 + kwb + 4 + tq];                   \
            }                                                                  \
            _Pragma("unroll")                                                  \
            for (int mi = 0; mi < 4; mi++)                                     \
                _Pragma("unroll")                                              \
                for (int ni = 0; ni < 4; ni++)                                 \
                    mma_f16(acc[mi][ni], af[mi], bf[ni][0], bf[ni][1]);        \
        }                                                                      \
        buf ^= 1;                                                              \
    }

// ---------------------------------------------------------------------------
// Fused QKV projection GEMM (fp16 out). grid.x in [0,18): mat = bx/6.
// ---------------------------------------------------------------------------
__global__ __launch_bounds__(256, 2) void gemm_qkv_fused(
    const __half* __restrict__ A, const __half* __restrict__ Wall,
    const float* __restrict__ bq, const float* __restrict__ bk,
    const float* __restrict__ bv,
    __half* __restrict__ Cq, __half* __restrict__ Ck, __half* __restrict__ Cv,
    int M)
{
    __shared__ __align__(16) uint32_t As[2 * 128 * 20];
    __shared__ __align__(16) uint32_t Ws[2 * 128 * 20];

    const int tid  = threadIdx.x;
    const int lane = tid & 31;
    const int warp = tid >> 5;
    const int wm   = (warp >> 2) * 64;
    const int wn   = (warp & 3) * 32;
    const int g    = lane >> 2;
    const int tq   = lane & 3;

    const int mat = blockIdx.x / 6;
    const int bn  = (blockIdx.x % 6) * 128;
    const int bm  = blockIdx.y * 128;

    const float* bias = (mat == 0) ? bq : (mat == 1) ? bk : bv;
    uint32_t* C16 = (uint32_t*)((mat == 0) ? Cq : (mat == 1) ? Ck : Cv);
    const uint32_t* Aw = (const uint32_t*)A;
    const uint32_t* Ww = (const uint32_t*)(Wall + (size_t)mat * DIM * DIM);

    float acc[4][4][4];
#pragma unroll
    for (int mi = 0; mi < 4; mi++)
#pragma unroll
        for (int ni = 0; ni < 4; ni++)
#pragma unroll
            for (int j = 0; j < 4; j++) acc[mi][ni][j] = 0.f;

    GEMM_MAINLOOP(Aw, Ww, (DIM >> 1))

#pragma unroll
    for (int ni = 0; ni < 4; ni++) {
        const int col = bn + wn + ni * 8 + 2 * tq;
        const float2 bb = *(const float2*)(bias + col);
#pragma unroll
        for (int mi = 0; mi < 4; mi++) {
            const int row = bm + wm + mi * 16 + g;
            C16[((size_t)row * DIM + col) >> 1] =
                pk2(acc[mi][ni][0] + bb.x, acc[mi][ni][1] + bb.y);
            C16[((size_t)(row + 8) * DIM + col) >> 1] =
                pk2(acc[mi][ni][2] + bb.x, acc[mi][ni][3] + bb.y);
        }
    }
}

// ---------------------------------------------------------------------------
// O-projection GEMM (fp16 in, fp32 out), double-buffered mainloop.
// ---------------------------------------------------------------------------
__global__ __launch_bounds__(256, 2) void gemm_ff16(
    const __half* __restrict__ A, const __half* __restrict__ W,
    const float* __restrict__ bias, float* __restrict__ C,
    int M, int N, int K)
{
    __shared__ __align__(16) uint32_t As[2 * 128 * 20];
    __shared__ __align__(16) uint32_t Ws[2 * 128 * 20];

    const int tid  = threadIdx.x;
    const int lane = tid & 31;
    const int warp = tid >> 5;
    const int wm   = (warp >> 2) * 64;
    const int wn   = (warp & 3) * 32;
    const int g    = lane >> 2;
    const int tq   = lane & 3;

    const int bm = blockIdx.y * 128;
    const int bn = blockIdx.x * 128;

    const uint32_t* Aw = (const uint32_t*)A;
    const uint32_t* Ww = (const uint32_t*)W;

    float acc[4][4][4];
#pragma unroll
    for (int mi = 0; mi < 4; mi++)
#pragma unroll
        for (int ni = 0; ni < 4; ni++)
#pragma unroll
            for (int j = 0; j < 4; j++) acc[mi][ni][j] = 0.f;

    GEMM_MAINLOOP(Aw, Ww, (K >> 1))

#pragma unroll
    for (int ni = 0; ni < 4; ni++) {
        const int col = bn + wn + ni * 8 + 2 * tq;
        const float2 bb = *(const float2*)(bias + col);
#pragma unroll
        for (int mi = 0; mi < 4; mi++) {
            const int row = bm + wm + mi * 16 + g;
            float2 v0, v1;
            v0.x = acc[mi][ni][0] + bb.x;
            v0.y = acc[mi][ni][1] + bb.y;
            v1.x = acc[mi][ni][2] + bb.x;
            v1.y = acc[mi][ni][3] + bb.y;
            *(float2*)(C + (size_t)row * N + col)       = v0;
            *(float2*)(C + (size_t)(row + 8) * N + col) = v1;
        }
    }
}

// ---------------------------------------------------------------------------
// Flash attention v12 (unchanged): no online max, tensor-pipe l,
// double-buffered K/V, one barrier/iter, fp16 in/out.
// ---------------------------------------------------------------------------
__global__ __launch_bounds__(256, 2) void flash_attn_f16_v12(
    const __half* __restrict__ Q, const __half* __restrict__ K,
    const __half* __restrict__ V, __half* __restrict__ O)
{
    extern __shared__ uint32_t usm[];
    uint32_t* Qs = usm;              // [128][28]
    uint32_t* Ks = usm + 3584;       // [2][64][28]
    uint32_t* Vt = usm + 7168;       // [2][56][36]

    const int tid  = threadIdx.x;
    const int lane = tid & 31;
    const int w    = tid >> 5;
    const int g    = lane >> 2;
    const int tq   = lane & 3;
    const int qb   = w * 16;

    const int h  = blockIdx.y;
    const int b  = blockIdx.z;
    const int q0 = blockIdx.x * BQ;

    const uint32_t* Qw = (const uint32_t*)Q + ((size_t)(b * SEQ + q0)) * 384 + h * 24;
    const uint32_t* Kw = (const uint32_t*)K + (size_t)b * SEQ * 384 + h * 24;
    const uint32_t* Vw = (const uint32_t*)V + (size_t)b * SEQ * 384 + h * 24;

    int kr[3], ku[3], vj[3], vdp[3];
#pragma unroll
    for (int i = 0; i < 3; i++) {
        int idx = tid + i * 256;
        kr[i] = idx / 12; ku[i] = idx % 12;
        vj[i] = idx / 24; vdp[i] = idx % 24;
    }

#pragma unroll
    for (int i = 0; i < 6; i++) {
        int idx = tid + i * 256;
        int r = idx / 12, u = idx % 12;
        uint2 qv = *(const uint2*)(Qw + (size_t)r * 384 + u * 2);
        *(uint2*)&Qs[r * 28 + u * 2] = qv;
    }
    for (int t = tid; t < 576; t += 256) {
        int bufi = t / 288;
        int rr   = (t % 288) / 36 + 48;
        int cc   = t % 36;
        Vt[bufi * 2016 + rr * 36 + cc] = (rr == 48) ? pk2(1.f, 1.f) : 0u;
    }

    uint2 kpre[3];
    uint32_t vp0[3], vp1[3];
#pragma unroll
    for (int i = 0; i < 3; i++) {
        kpre[i] = *(const uint2*)(Kw + (size_t)kr[i] * 384 + ku[i] * 2);
        vp0[i]  = Vw[(size_t)(2 * vj[i])     * 384 + vdp[i]];
        vp1[i]  = Vw[(size_t)(2 * vj[i] + 1) * 384 + vdp[i]];
    }
    __syncthreads();

    uint32_t qf[3][4];
#pragma unroll
    for (int kt = 0; kt < 3; kt++) {
        const int kwb = kt * 8;
        qf[kt][0] = Qs[(qb + g) * 28 + kwb + tq];
        qf[kt][1] = Qs[(qb + 8 + g) * 28 + kwb + tq];
        qf[kt][2] = Qs[(qb + g) * 28 + kwb + 4 + tq];
        qf[kt][3] = Qs[(qb + 8 + g) * 28 + kwb + 4 + tq];
    }

    float oacc[7][4];
#pragma unroll
    for (int ni = 0; ni < 7; ni++)
#pragma unroll
        for (int j = 0; j < 4; j++) oacc[ni][j] = 0.f;

    const float CE = ATTN_SCALE * 1.4426950408889634f;

    for (int it = 0; it < NIT; it++) {
        uint32_t* Ksb = Ks + (it & 1) * 1792;
        uint32_t* Vtb = Vt + (it & 1) * 2016;

#pragma unroll
        for (int i = 0; i < 3; i++) {
            *(uint2*)&Ksb[kr[i] * 28 + ku[i] * 2] = kpre[i];
            Vtb[(2 * vdp[i])     * 36 + vj[i]] = prmt(vp0[i], vp1[i], 0x5410u);
            Vtb[(2 * vdp[i] + 1) * 36 + vj[i]] = prmt(vp0[i], vp1[i], 0x7632u);
        }
        __syncthreads();

        if (it + 1 < NIT) {
            const int kv1 = (it + 1) * BKV;
#pragma unroll
            for (int i = 0; i < 3; i++) {
                kpre[i] = *(const uint2*)(Kw + (size_t)(kv1 + kr[i]) * 384 + ku[i] * 2);
                vp0[i]  = Vw[(size_t)(kv1 + 2 * vj[i])     * 384 + vdp[i]];
                vp1[i]  = Vw[(size_t)(kv1 + 2 * vj[i] + 1) * 384 + vdp[i]];
            }
        }

        float sacc[8][4];
#pragma unroll
        for (int ni = 0; ni < 8; ni++)
#pragma unroll
            for (int j = 0; j < 4; j++) sacc[ni][j] = 0.f;

#pragma unroll
        for (int kt = 0; kt < 3; kt++) {
            const int kwb = kt * 8;
#pragma unroll
            for (int ni = 0; ni < 8; ni++) {
                const int n = ni * 8;
                uint32_t b0 = Ksb[(n + g) * 28 + kwb + tq];
                uint32_t b1 = Ksb[(n + g) * 28 + kwb + 4 + tq];
                mma_f16(sacc[ni], qf[kt], b0, b1);
            }
        }

        uint32_t pf[4][4];
#pragma unroll
        for (int kt = 0; kt < 4; kt++) {
            float p00 = fexp2(sacc[2*kt][0]   * CE);
            float p01 = fexp2(sacc[2*kt][1]   * CE);
            float p02 = fexp2(sacc[2*kt][2]   * CE);
            float p03 = fexp2(sacc[2*kt][3]   * CE);
            float p10 = fexp2(sacc[2*kt+1][0] * CE);
            float p11 = fexp2(sacc[2*kt+1][1] * CE);
            float p12 = fexp2(sacc[2*kt+1][2] * CE);
            float p13 = fexp2(sacc[2*kt+1][3] * CE);
            pf[kt][0] = pk2(p00, p01);
            pf[kt][1] = pk2(p02, p03);
            pf[kt][2] = pk2(p10, p11);
            pf[kt][3] = pk2(p12, p13);
        }

#pragma unroll
        for (int kt = 0; kt < 4; kt++) {
            const int kwb = kt * 8;
#pragma unroll
            for (int ni = 0; ni < 7; ni++) {
                const int n = ni * 8;
                uint32_t b0 = Vtb[(n + g) * 36 + kwb + tq];
                uint32_t b1 = Vtb[(n + g) * 36 + kwb + 4 + tq];
                mma_f16(oacc[ni], pf[kt], b0, b1);
            }
        }
    }

    const float l0 = __shfl_sync(0xffffffffu, oacc[6][0], lane & ~3);
    const float l1 = __shfl_sync(0xffffffffu, oacc[6][2], lane & ~3);
    const float inv0 = 1.f / l0;
    const float inv1 = 1.f / l1;
    uint32_t* Ow = (uint32_t*)O + ((size_t)(b * SEQ + q0 + qb)) * 384 + h * 24;
#pragma unroll
    for (int ni = 0; ni < 6; ni++) {
        const int cw = ni * 4 + tq;
        Ow[(size_t)g * 384 + cw] =
            pk2(oacc[ni][0] * inv0, oacc[ni][1] * inv0);
        Ow[(size_t)(g + 8) * 384 + cw] =
            pk2(oacc[ni][2] * inv1, oacc[ni][3] * inv1);
    }
}

// ---------------------------------------------------------------------------
// launch
// ---------------------------------------------------------------------------
extern "C" void kernel_launch(void* const* d_in, const int* in_sizes, int n_in,
                              void* d_out, int out_size)
{
    const float* x  = (const float*)d_in[0];
    const float* Wq = (const float*)d_in[1];
    const float* bq = (const float*)d_in[2];
    const float* Wk = (const float*)d_in[3];
    const float* bk = (const float*)d_in[4];
    const float* Wv = (const float*)d_in[5];
    const float* bv = (const float*)d_in[6];
    const float* Wo = (const float*)d_in[7];
    const float* bo = (const float*)d_in[8];
    float* out = (float*)d_out;

    const int M = in_sizes[0] / DIM;   // B*S = 8192
    const int B = M / SEQ;             // 4

    __half *x16, *w16, *qp, *kp, *vp, *aop;
    cudaGetSymbolAddress((void**)&x16, g_x16);
    cudaGetSymbolAddress((void**)&w16, g_w16);
    cudaGetSymbolAddress((void**)&qp,  g_q);
    cudaGetSymbolAddress((void**)&kp,  g_k);
    cudaGetSymbolAddress((void**)&vp,  g_v);
    cudaGetSymbolAddress((void**)&aop, g_ao);

    const int attn_smem = 11200 * 4;   // 44800 bytes

    // prep: fp32 -> fp16
    conv_x_f16<<<(M * DIM / 4) / 256, 256>>>((const float4*)x, (uint2*)x16);
    conv_w_f16<<<dim3((DIM * DIM / 4) / 256, 4), 256>>>(Wq, Wk, Wv, Wo, w16);

    // fused QKV projection: grid (18, 64) = 1152 CTAs
    dim3 qkvgrid(3 * DIM / 128, M / 128);
    gemm_qkv_fused<<<qkvgrid, 256>>>(x16, w16, bq, bk, bv, qp, kp, vp, M);

    dim3 agrid(SEQ / BQ, NHEAD, B);    // (16, 16, 4)
    flash_attn_f16_v12<<<agrid, 256, attn_smem>>>(qp, kp, vp, aop);

    dim3 ogrid(DIM / 128, M / 128);    // (6, 64)
    gemm_ff16<<<ogrid, 256>>>(aop, w16 + 3 * DIM * DIM, bo, out, M, DIM, DIM);
}